// round 2
// baseline (speedup 1.0000x reference)
#include <cuda_runtime.h>
#include <cuda_bf16.h>

#define SEQ    32768
#define WD     512
#define HID    1024
#define NCTA   32          // CTAs total (both folds share them)
#define RPC    16          // rows of W1/W3 per CTA; cols of W2 per CTA
#define THREADS 256

struct Smem {
    float W1s[RPC][HID];     // 64 KB  W1 row slice
    float W2s[RPC][HID];     // 64 KB  W2 col slice, transposed: [local col][t-row]
    float W3s[RPC][HID];     // 64 KB  W3 row slice
    float b2s[HID];
    float u_s[HID];          // tanh(t + b2), reused fold0 then fold1
    float p_s[2][WD];        // per-fold p
    float x_s[2][2][WD];     // [fold][buf] double-buffered x_i
    float a_s[2][RPC];
    float b1s[RPC];
    float b3s[RPC];
};

__device__ float        g_t[2][2][HID];          // [fold][buf] t accumulators
__device__ float        g_pv[2][WD];             // [fold] p vector
__device__ unsigned int g_flags[NCTA * 32];      // per-CTA monotonic epoch (128B stride)

__device__ __forceinline__ void st_release(unsigned int* p, unsigned int v) {
    asm volatile("st.release.gpu.global.u32 [%0], %1;" :: "l"(p), "r"(v) : "memory");
}
__device__ __forceinline__ unsigned int ld_acquire(const unsigned int* p) {
    unsigned int v;
    asm volatile("ld.acquire.gpu.global.u32 %0, [%1];" : "=r"(v) : "l"(p) : "memory");
    return v;
}

__global__ void __launch_bounds__(THREADS, 1)
rnn_fold_kernel(const float* __restrict__ input,
                const float* __restrict__ input2,
                const float* __restrict__ W1g, const float* __restrict__ b1g,
                const float* __restrict__ W2g, const float* __restrict__ b2g,
                const float* __restrict__ W3g, const float* __restrict__ b3g)
{
    extern __shared__ float smem_raw[];
    Smem& s = *reinterpret_cast<Smem*>(smem_raw);

    const int tid  = threadIdx.x;
    const int lane = tid & 31;
    const int warp = tid >> 5;
    const int k    = blockIdx.x;
    const int r0   = k * RPC;

    // ---------------- load resident weight slices ----------------
    {
        const float4* src1 = reinterpret_cast<const float4*>(W1g + (size_t)r0 * HID);
        float4*       dst1 = reinterpret_cast<float4*>(&s.W1s[0][0]);
        const float4* src3 = reinterpret_cast<const float4*>(W3g + (size_t)r0 * HID);
        float4*       dst3 = reinterpret_cast<float4*>(&s.W3s[0][0]);
        for (int i = tid; i < RPC * HID / 4; i += THREADS) { dst1[i] = src1[i]; dst3[i] = src3[i]; }

        const int c0 = k * RPC;
        for (int r = tid; r < HID; r += THREADS) {
            const float4* wr = reinterpret_cast<const float4*>(W2g + (size_t)r * WD + c0);
            #pragma unroll
            for (int q = 0; q < 4; ++q) {
                float4 v = wr[q];
                s.W2s[4*q+0][r] = v.x; s.W2s[4*q+1][r] = v.y;
                s.W2s[4*q+2][r] = v.z; s.W2s[4*q+3][r] = v.w;
            }
        }
        for (int i = tid; i < HID; i += THREADS) s.b2s[i] = b2g[i];
        if (tid < RPC) { s.b1s[tid] = b1g[r0 + tid]; s.b3s[tid] = b3g[r0 + tid]; }

        // p0 = x[0]; x buffer 1 = x[1] for both folds
        for (int i = tid; i < WD / 2; i += THREADS) {
            reinterpret_cast<float2*>(s.p_s[0])[i]    = reinterpret_cast<const float2*>(input)[i];
            reinterpret_cast<float2*>(s.x_s[0][1])[i] = reinterpret_cast<const float2*>(input + WD)[i];
            reinterpret_cast<float2*>(s.p_s[1])[i]    = reinterpret_cast<const float2*>(input2)[i];
            reinterpret_cast<float2*>(s.x_s[1][1])[i] = reinterpret_cast<const float2*>(input2 + WD)[i];
        }
        // zero both t accumulator buffers for both folds (our chunk)
        if (tid < HID / NCTA) {
            g_t[0][0][k * (HID / NCTA) + tid] = 0.0f;
            g_t[0][1][k * (HID / NCTA) + tid] = 0.0f;
            g_t[1][0][k * (HID / NCTA) + tid] = 0.0f;
            g_t[1][1][k * (HID / NCTA) + tid] = 0.0f;
        }
    }

    unsigned int* my_flag = &g_flags[(unsigned)k * 32u];
    // monotonic epoch base: equal across CTAs at launch start (replay-safe)
    const unsigned int base = ld_acquire(my_flag);
    unsigned int ep = base;

    auto arrive = [&](unsigned int e) {
        __syncthreads();                       // all threads' prior work happens-before
        if (tid == 0) st_release(my_flag, e);  // publish (release)
    };
    auto wait_all = [&](unsigned int e) {
        if (warp == 0) {
            const unsigned int* fp = &g_flags[(unsigned)lane * 32u];
            unsigned int v;
            do { v = ld_acquire(fp); } while ((int)(v - e) < 0);
        }
        __syncthreads();
    };

    const int row = warp * 2 + (lane >> 4);   // local W1/W3 output row
    const int lg  = lane & 15;                // lane within 16-lane dot group

    auto stage1 = [&](int f, int buf) {
        const float4* w1r = reinterpret_cast<const float4*>(&s.W1s[row][0]);
        const float4* pp  = reinterpret_cast<const float4*>(s.p_s[f]);
        const float4* xx  = reinterpret_cast<const float4*>(s.x_s[f][buf]);
        float acc = 0.0f;
        #pragma unroll
        for (int q = 0; q < 8; ++q) {
            int j = lg + 16 * q;
            float4 w = w1r[j]; float4 h = pp[j];
            acc += w.x*h.x + w.y*h.y + w.z*h.z + w.w*h.w;
        }
        #pragma unroll
        for (int q = 8; q < 16; ++q) {
            int j = lg + 16 * q;
            float4 w = w1r[j]; float4 h = xx[j - 128];
            acc += w.x*h.x + w.y*h.y + w.z*h.z + w.w*h.w;
        }
        acc += __shfl_down_sync(0xffffffffu, acc, 8);
        acc += __shfl_down_sync(0xffffffffu, acc, 4);
        acc += __shfl_down_sync(0xffffffffu, acc, 2);
        acc += __shfl_down_sync(0xffffffffu, acc, 1);
        if (lg == 0) s.a_s[f][row] = fmaxf(acc + s.b1s[row], 0.0f);
    };

    auto stage1b = [&](int f, int buf) {
        const int rb = ((tid + (k << 3)) & 255);   // stagger atomics per CTA
        float4 pt = make_float4(0.f, 0.f, 0.f, 0.f);
        #pragma unroll
        for (int c = 0; c < RPC; ++c) {
            float av = s.a_s[f][c];                 // LDS broadcast
            float4 w = reinterpret_cast<const float4*>(&s.W2s[c][0])[rb];
            pt.x += w.x * av; pt.y += w.y * av; pt.z += w.z * av; pt.w += w.w * av;
        }
        float* tg = &g_t[f][buf][0] + rb * 4;
        atomicAdd(tg + 0, pt.x); atomicAdd(tg + 1, pt.y);
        atomicAdd(tg + 2, pt.z); atomicAdd(tg + 3, pt.w);
    };

    auto stage2 = [&](int f, int buf) {
        float4 t4  = __ldcg(reinterpret_cast<const float4*>(&g_t[f][buf][0]) + tid);
        float4 b24 = reinterpret_cast<const float4*>(s.b2s)[tid];
        float4 u4;
        u4.x = tanhf(t4.x + b24.x); u4.y = tanhf(t4.y + b24.y);
        u4.z = tanhf(t4.z + b24.z); u4.w = tanhf(t4.w + b24.w);
        reinterpret_cast<float4*>(s.u_s)[tid] = u4;
        __syncthreads();
        const float4* w3r = reinterpret_cast<const float4*>(&s.W3s[row][0]);
        const float4* uu  = reinterpret_cast<const float4*>(s.u_s);
        float acc = 0.0f;
        #pragma unroll
        for (int q = 0; q < 16; ++q) {
            int j = lg + 16 * q;
            float4 w = w3r[j]; float4 h = uu[j];
            acc += w.x*h.x + w.y*h.y + w.z*h.z + w.w*h.w;
        }
        acc += __shfl_down_sync(0xffffffffu, acc, 8);
        acc += __shfl_down_sync(0xffffffffu, acc, 4);
        acc += __shfl_down_sync(0xffffffffu, acc, 2);
        acc += __shfl_down_sync(0xffffffffu, acc, 1);
        if (lg == 0) g_pv[f][r0 + row] = tanhf(acc + s.b3s[row]);
    };

    arrive(++ep);        // init: t zeroing visible grid-wide
    wait_all(ep);

    for (int i = 1; i < SEQ; ++i) {
        const int buf = i & 1;

        // ---- fold 0: stage 1 + partial-t reduction ----
        stage1(0, buf);
        __syncthreads();
        stage1b(0, buf);
        arrive(++ep);                       // E1: f0 t-partials published

        // ---- fold 1: stage 1 (hides f0 barrier latency) ----
        stage1(1, buf);
        __syncthreads();
        // prefetch next x rows (both folds) + zero next-step t buffers
        if (i + 1 < SEQ) {
            reinterpret_cast<float2*>(s.x_s[0][buf ^ 1])[tid] =
                reinterpret_cast<const float2*>(input  + (size_t)(i + 1) * WD)[tid];
            reinterpret_cast<float2*>(s.x_s[1][buf ^ 1])[tid] =
                reinterpret_cast<const float2*>(input2 + (size_t)(i + 1) * WD)[tid];
        }
        if (tid < HID / NCTA) {
            g_t[0][buf ^ 1][k * (HID / NCTA) + tid] = 0.0f;
            g_t[1][buf ^ 1][k * (HID / NCTA) + tid] = 0.0f;
        }
        stage1b(1, buf);
        arrive(++ep);                       // E2: f1 t-partials (+ zeros) published

        wait_all(ep - 1);                   // wait E1 (f0 t complete)
        stage2(0, buf);
        arrive(++ep);                       // E3: f0 p published

        wait_all(ep - 1);                   // wait E2 (f1 t complete)
        stage2(1, buf);
        arrive(++ep);                       // E4: f1 p published

        if (i < SEQ - 1) {
            wait_all(ep);                   // E4 >= E3: both p vectors complete
            reinterpret_cast<float2*>(s.p_s[0])[tid] =
                __ldcg(reinterpret_cast<const float2*>(&g_pv[0][0]) + tid);
            reinterpret_cast<float2*>(s.p_s[1])[tid] =
                __ldcg(reinterpret_cast<const float2*>(&g_pv[1][0]) + tid);
            __syncthreads();
        }
    }
}

__global__ void logits_kernel(const float* __restrict__ W4g,
                              const float* __restrict__ b4g,
                              float* __restrict__ out)
{
    __shared__ float lg[5];
    const int tid = threadIdx.x, warp = tid >> 5, lane = tid & 31;
    if (warp < 5) {
        float acc = 0.0f;
        const float* w = W4g + warp * (2 * WD);
        for (int j = lane; j < 2 * WD; j += 32) {
            float h = (j < WD) ? g_pv[0][j] : g_pv[1][j - WD];
            acc += w[j] * h;
        }
        #pragma unroll
        for (int o = 16; o > 0; o >>= 1) acc += __shfl_down_sync(0xffffffffu, acc, o);
        if (lane == 0) lg[warp] = acc + b4g[warp];
    }
    __syncthreads();
    if (tid == 0) {
        float m = lg[0];
        #pragma unroll
        for (int c = 1; c < 5; ++c) m = fmaxf(m, lg[c]);
        float ssum = 0.0f;
        #pragma unroll
        for (int c = 0; c < 5; ++c) ssum += expf(lg[c] - m);
        float lse = m + logf(ssum);
        #pragma unroll
        for (int c = 0; c < 5; ++c) out[c] = lg[c] - lse;
    }
}

extern "C" void kernel_launch(void* const* d_in, const int* in_sizes, int n_in,
                              void* d_out, int out_size)
{
    const float* input  = (const float*)d_in[0];
    const float* input2 = (const float*)d_in[1];
    const int off = (n_in >= 11) ? 3 : 2;
    const float* W1 = (const float*)d_in[off + 0];
    const float* b1 = (const float*)d_in[off + 1];
    const float* W2 = (const float*)d_in[off + 2];
    const float* b2 = (const float*)d_in[off + 3];
    const float* W3 = (const float*)d_in[off + 4];
    const float* b3 = (const float*)d_in[off + 5];
    const float* W4 = (const float*)d_in[off + 6];
    const float* b4 = (const float*)d_in[off + 7];

    cudaFuncSetAttribute(rnn_fold_kernel,
                         cudaFuncAttributeMaxDynamicSharedMemorySize,
                         (int)sizeof(Smem));
    rnn_fold_kernel<<<NCTA, THREADS, sizeof(Smem)>>>(
        input, input2, W1, b1, W2, b2, W3, b3);
    logits_kernel<<<1, 160>>>(W4, b4, (float*)d_out);
}

// round 3
// speedup vs baseline: 1.3847x; 1.3847x over previous
#include <cuda_runtime.h>
#include <cuda_bf16.h>

#define SEQ    32768
#define WD     512
#define HID    1024
#define NCTA   32          // CTAs per fold
#define NFOLD  2
#define RPC    16          // rows of W1/W3 per CTA; cols of W2 per CTA
#define THREADS 256

struct Smem {
    float W1s[RPC][HID];     // 64 KB
    float W2s[RPC][HID];     // 64 KB (transposed col slice: [local col][t-row])
    float W3s[RPC][HID];     // 64 KB
    float u_s[HID];
    float b2s[HID];
    float p_s[WD];
    float x_s[2][WD];
    float a_s[RPC];
    float b1s[RPC];
    float b3s[RPC];
};

__device__ float        g_t[NFOLD][2][HID];
__device__ float        g_pv[NFOLD][WD];
__device__ unsigned int g_flags[NFOLD * NCTA * 32];   // 128B-strided epoch flags

__device__ __forceinline__ void st_release(unsigned int* p, unsigned int v) {
    asm volatile("st.release.gpu.global.u32 [%0], %1;" :: "l"(p), "r"(v) : "memory");
}
__device__ __forceinline__ unsigned int ld_acquire(const unsigned int* p) {
    unsigned int v;
    asm volatile("ld.acquire.gpu.global.u32 %0, [%1];" : "=r"(v) : "l"(p) : "memory");
    return v;
}

__global__ void noop_kernel() {}

__global__ void __launch_bounds__(THREADS, 1)
rnn_fold_kernel(const float* __restrict__ input,
                const float* __restrict__ input2,
                const float* __restrict__ W1g, const float* __restrict__ b1g,
                const float* __restrict__ W2g, const float* __restrict__ b2g,
                const float* __restrict__ W3g, const float* __restrict__ b3g)
{
    extern __shared__ float smem_raw[];
    Smem& s = *reinterpret_cast<Smem*>(smem_raw);

    const int tid  = threadIdx.x;
    const int lane = tid & 31;
    const int warp = tid >> 5;
    const int cta  = blockIdx.x;
    const int fold = cta / NCTA;
    const int k    = cta % NCTA;
    const int r0   = k * RPC;
    const float* xsrc = (fold == 0) ? input : input2;

    // ---------------- load resident weight slices ----------------
    {
        const float4* src1 = reinterpret_cast<const float4*>(W1g + (size_t)r0 * HID);
        float4*       dst1 = reinterpret_cast<float4*>(&s.W1s[0][0]);
        const float4* src3 = reinterpret_cast<const float4*>(W3g + (size_t)r0 * HID);
        float4*       dst3 = reinterpret_cast<float4*>(&s.W3s[0][0]);
        for (int i = tid; i < RPC * HID / 4; i += THREADS) { dst1[i] = src1[i]; dst3[i] = src3[i]; }

        const int c0 = k * RPC;
        for (int r = tid; r < HID; r += THREADS) {
            const float4* wr = reinterpret_cast<const float4*>(W2g + (size_t)r * WD + c0);
            #pragma unroll
            for (int q = 0; q < 4; ++q) {
                float4 v = wr[q];
                s.W2s[4*q+0][r] = v.x; s.W2s[4*q+1][r] = v.y;
                s.W2s[4*q+2][r] = v.z; s.W2s[4*q+3][r] = v.w;
            }
        }
        for (int i = tid; i < HID; i += THREADS) s.b2s[i] = b2g[i];
        if (tid < RPC) { s.b1s[tid] = b1g[r0 + tid]; s.b3s[tid] = b3g[r0 + tid]; }

        for (int i = tid; i < WD / 2; i += THREADS) {
            reinterpret_cast<float2*>(s.p_s)[i]    = reinterpret_cast<const float2*>(xsrc)[i];
            reinterpret_cast<float2*>(s.x_s[1])[i] = reinterpret_cast<const float2*>(xsrc + WD)[i];
        }
        if (tid < HID / NCTA) {
            g_t[fold][0][k * (HID / NCTA) + tid] = 0.0f;
            g_t[fold][1][k * (HID / NCTA) + tid] = 0.0f;
        }
    }

    unsigned int*       my_flag   = &g_flags[(unsigned)(fold * NCTA + k) * 32u];
    const unsigned int  fold_base = (unsigned)(fold * NCTA) * 32u;
    const unsigned int  base      = ld_acquire(my_flag);   // replay-safe monotonic epoch
    unsigned int ep = base;

    auto arrive = [&](unsigned int e) {
        __syncthreads();
        if (tid == 0) st_release(my_flag, e);
    };
    auto wait_all = [&](unsigned int e) {
        if (warp == 0) {
            const unsigned int* fp = &g_flags[fold_base + (unsigned)lane * 32u];
            unsigned int v;
            do { v = ld_acquire(fp); } while ((int)(v - e) < 0);
        }
        __syncthreads();
    };

    const int row = warp * 2 + (lane >> 4);
    const int lg  = lane & 15;

    arrive(++ep);                 // init: t zeroing visible fold-wide
    wait_all(ep);

    for (int i = 1; i < SEQ; ++i) {
        const int buf = i & 1;

        // ---- stage 1: a = relu(W1 [p;x_i] + b1) (row slice) ----
        {
            const float4* w1r = reinterpret_cast<const float4*>(&s.W1s[row][0]);
            const float4* pp  = reinterpret_cast<const float4*>(s.p_s);
            const float4* xx  = reinterpret_cast<const float4*>(s.x_s[buf]);
            float acc = 0.0f;
            #pragma unroll
            for (int q = 0; q < 8; ++q) {
                int j = lg + 16 * q;
                float4 w = w1r[j]; float4 h = pp[j];
                acc += w.x*h.x + w.y*h.y + w.z*h.z + w.w*h.w;
            }
            #pragma unroll
            for (int q = 8; q < 16; ++q) {
                int j = lg + 16 * q;
                float4 w = w1r[j]; float4 h = xx[j - 128];
                acc += w.x*h.x + w.y*h.y + w.z*h.z + w.w*h.w;
            }
            acc += __shfl_down_sync(0xffffffffu, acc, 8);
            acc += __shfl_down_sync(0xffffffffu, acc, 4);
            acc += __shfl_down_sync(0xffffffffu, acc, 2);
            acc += __shfl_down_sync(0xffffffffu, acc, 1);
            if (lg == 0) s.a_s[row] = fmaxf(acc + s.b1s[row], 0.0f);
        }
        __syncthreads();

        // prefetch next x + zero next-step t buffer
        if (i + 1 < SEQ) {
            reinterpret_cast<float2*>(s.x_s[(i + 1) & 1])[tid] =
                reinterpret_cast<const float2*>(xsrc + (size_t)(i + 1) * WD)[tid];
        }
        if (tid < HID / NCTA) g_t[fold][(i + 1) & 1][k * (HID / NCTA) + tid] = 0.0f;

        // ---- stage 1b: partial t += W2[:, our cols] @ a_slice (RED to L2) ----
        {
            const int rb = ((tid + (k << 3)) & 255);
            float4 pt = make_float4(0.f, 0.f, 0.f, 0.f);
            #pragma unroll
            for (int c = 0; c < RPC; ++c) {
                float av = s.a_s[c];
                float4 w = reinterpret_cast<const float4*>(&s.W2s[c][0])[rb];
                pt.x += w.x * av; pt.y += w.y * av; pt.z += w.z * av; pt.w += w.w * av;
            }
            float* tg = &g_t[fold][buf][0] + rb * 4;
            atomicAdd(tg + 0, pt.x); atomicAdd(tg + 1, pt.y);
            atomicAdd(tg + 2, pt.z); atomicAdd(tg + 3, pt.w);
        }

        arrive(++ep);             // barrier 1 arrive: t partials published
        wait_all(ep);             // t fully reduced

        // ---- stage 2: u = tanh(t+b2); p-rows = tanh(W3 u + b3) ----
        {
            float4 t4  = __ldcg(reinterpret_cast<const float4*>(&g_t[fold][buf][0]) + tid);
            float4 b24 = reinterpret_cast<const float4*>(s.b2s)[tid];
            float4 u4;
            u4.x = tanhf(t4.x + b24.x); u4.y = tanhf(t4.y + b24.y);
            u4.z = tanhf(t4.z + b24.z); u4.w = tanhf(t4.w + b24.w);
            reinterpret_cast<float4*>(s.u_s)[tid] = u4;
        }
        __syncthreads();
        {
            const float4* w3r = reinterpret_cast<const float4*>(&s.W3s[row][0]);
            const float4* uu  = reinterpret_cast<const float4*>(s.u_s);
            float acc = 0.0f;
            #pragma unroll
            for (int q = 0; q < 16; ++q) {
                int j = lg + 16 * q;
                float4 w = w3r[j]; float4 h = uu[j];
                acc += w.x*h.x + w.y*h.y + w.z*h.z + w.w*h.w;
            }
            acc += __shfl_down_sync(0xffffffffu, acc, 8);
            acc += __shfl_down_sync(0xffffffffu, acc, 4);
            acc += __shfl_down_sync(0xffffffffu, acc, 2);
            acc += __shfl_down_sync(0xffffffffu, acc, 1);
            if (lg == 0) g_pv[fold][r0 + row] = tanhf(acc + s.b3s[row]);
        }

        if (i < SEQ - 1) {
            arrive(++ep);         // barrier 2: p published
            wait_all(ep);
            reinterpret_cast<float2*>(s.p_s)[tid] =
                __ldcg(reinterpret_cast<const float2*>(&g_pv[fold][0]) + tid);
            __syncthreads();
        }
    }
}

__global__ void logits_kernel(const float* __restrict__ W4g,
                              const float* __restrict__ b4g,
                              float* __restrict__ out)
{
    __shared__ float lg[5];
    const int tid = threadIdx.x, warp = tid >> 5, lane = tid & 31;
    if (warp < 5) {
        float acc = 0.0f;
        const float* w = W4g + warp * (2 * WD);
        for (int j = lane; j < 2 * WD; j += 32) {
            float h = (j < WD) ? g_pv[0][j] : g_pv[1][j - WD];
            acc += w[j] * h;
        }
        #pragma unroll
        for (int o = 16; o > 0; o >>= 1) acc += __shfl_down_sync(0xffffffffu, acc, o);
        if (lane == 0) lg[warp] = acc + b4g[warp];
    }
    __syncthreads();
    if (tid == 0) {
        float m = lg[0];
        #pragma unroll
        for (int c = 1; c < 5; ++c) m = fmaxf(m, lg[c]);
        float ssum = 0.0f;
        #pragma unroll
        for (int c = 0; c < 5; ++c) ssum += expf(lg[c] - m);
        float lse = m + logf(ssum);
        #pragma unroll
        for (int c = 0; c < 5; ++c) out[c] = lg[c] - lse;
    }
}

extern "C" void kernel_launch(void* const* d_in, const int* in_sizes, int n_in,
                              void* d_out, int out_size)
{
    const float* input  = (const float*)d_in[0];
    const float* input2 = (const float*)d_in[1];
    const int off = (n_in >= 11) ? 3 : 2;
    const float* W1 = (const float*)d_in[off + 0];
    const float* b1 = (const float*)d_in[off + 1];
    const float* W2 = (const float*)d_in[off + 2];
    const float* b2 = (const float*)d_in[off + 3];
    const float* W3 = (const float*)d_in[off + 4];
    const float* b3 = (const float*)d_in[off + 5];
    const float* W4 = (const float*)d_in[off + 6];
    const float* b4 = (const float*)d_in[off + 7];

    cudaFuncSetAttribute(rnn_fold_kernel,
                         cudaFuncAttributeMaxDynamicSharedMemorySize,
                         (int)sizeof(Smem));

    // Launch order [noop, fold, logits, noop]: period 4 puts global launch
    // index 5 (ncu -s 5 -c 1) on the FOLD kernel so we finally profile it.
    noop_kernel<<<1, 32>>>();
    rnn_fold_kernel<<<NFOLD * NCTA, THREADS, sizeof(Smem)>>>(
        input, input2, W1, b1, W2, b2, W3, b3);
    logits_kernel<<<1, 160>>>(W4, b4, (float*)d_out);
    noop_kernel<<<1, 32>>>();
}

// round 4
// speedup vs baseline: 1.3973x; 1.0091x over previous
#include <cuda_runtime.h>
#include <cuda_bf16.h>

#define SEQ    32768
#define WD     512
#define HID    1024
#define NCTA   32          // CTAs per fold
#define NFOLD  2
#define RPC    16          // rows of W1/W3 per CTA; cols of W2 per CTA
#define THREADS 256

struct Smem {
    float W2s[RPC][HID];     // 64 KB (transposed col slice: [local col][t-row])
    float u_s[HID];
    float b2s[HID];
    float p_s[WD];
    float x_s[2][WD];
    float a_s[RPC];
    float b1s[RPC];
    float b3s[RPC];
    float lgst[8];
};

__device__ float        g_t[NFOLD][2][HID];
__device__ float        g_pv[NFOLD][WD];
__device__ unsigned int g_flags[NFOLD * NCTA * 32];   // 128B-strided epoch flags

__device__ __forceinline__ void st_release(unsigned int* p, unsigned int v) {
    asm volatile("st.release.gpu.global.u32 [%0], %1;" :: "l"(p), "r"(v) : "memory");
}
__device__ __forceinline__ unsigned int ld_acquire(const unsigned int* p) {
    unsigned int v;
    asm volatile("ld.acquire.gpu.global.u32 %0, [%1];" : "=r"(v) : "l"(p) : "memory");
    return v;
}

// tanh with ~1e-7 abs error: 1 - 2/(e^{2x}+1). MUFU ex2 + fast div.
__device__ __forceinline__ float ftanh(float x) {
    float e = __expf(2.0f * x);
    return 1.0f - __fdividef(2.0f, e + 1.0f);
}

__global__ void __launch_bounds__(THREADS, 1)
rnn_fold_kernel(const float* __restrict__ input,
                const float* __restrict__ input2,
                const float* __restrict__ W1g, const float* __restrict__ b1g,
                const float* __restrict__ W2g, const float* __restrict__ b2g,
                const float* __restrict__ W3g, const float* __restrict__ b3g,
                const float* __restrict__ W4g, const float* __restrict__ b4g,
                float* __restrict__ out)
{
    extern __shared__ float smem_raw[];
    Smem& s = *reinterpret_cast<Smem*>(smem_raw);

    const int tid  = threadIdx.x;
    const int lane = tid & 31;
    const int warp = tid >> 5;
    const int cta  = blockIdx.x;
    const int fold = cta / NCTA;
    const int k    = cta % NCTA;
    const int r0   = k * RPC;
    const float* xsrc = (fold == 0) ? input : input2;

    const int row = warp * 2 + (lane >> 4);   // local W1/W3 output row
    const int lg  = lane & 15;                // lane within 16-lane dot group

    // ---------------- W1/W3 row slices -> registers (static, unrolled) ----------------
    float4 w1reg[16], w3reg[16];
    {
        const float4* w1row = reinterpret_cast<const float4*>(W1g + (size_t)(r0 + row) * HID);
        const float4* w3row = reinterpret_cast<const float4*>(W3g + (size_t)(r0 + row) * HID);
        #pragma unroll
        for (int q = 0; q < 16; ++q) {
            w1reg[q] = w1row[lg + 16 * q];
            w3reg[q] = w3row[lg + 16 * q];
        }
    }

    // ---------------- W2 col slice -> smem (transposed) ----------------
    {
        const int c0 = k * RPC;
        for (int r = tid; r < HID; r += THREADS) {
            const float4* wr = reinterpret_cast<const float4*>(W2g + (size_t)r * WD + c0);
            #pragma unroll
            for (int q = 0; q < 4; ++q) {
                float4 v = wr[q];
                s.W2s[4*q+0][r] = v.x; s.W2s[4*q+1][r] = v.y;
                s.W2s[4*q+2][r] = v.z; s.W2s[4*q+3][r] = v.w;
            }
        }
        for (int i = tid; i < HID; i += THREADS) s.b2s[i] = b2g[i];
        if (tid < RPC) { s.b1s[tid] = b1g[r0 + tid]; s.b3s[tid] = b3g[r0 + tid]; }

        for (int i = tid; i < WD / 2; i += THREADS) {
            reinterpret_cast<float2*>(s.p_s)[i]    = reinterpret_cast<const float2*>(xsrc)[i];
            reinterpret_cast<float2*>(s.x_s[1])[i] = reinterpret_cast<const float2*>(xsrc + WD)[i];
        }
        if (tid < HID / NCTA) {
            g_t[fold][0][k * (HID / NCTA) + tid] = 0.0f;
            g_t[fold][1][k * (HID / NCTA) + tid] = 0.0f;
        }
    }

    unsigned int*       my_flag   = &g_flags[(unsigned)cta * 32u];
    const unsigned int  fold_base = (unsigned)(fold * NCTA) * 32u;
    const unsigned int  base      = ld_acquire(my_flag);   // replay-safe monotonic epoch
    unsigned int ep = base;

    auto arrive = [&](unsigned int e) {
        __syncthreads();
        if (tid == 0) st_release(my_flag, e);
    };
    auto wait_fold = [&](unsigned int e) {
        if (warp == 0) {
            const unsigned int* fp = &g_flags[fold_base + (unsigned)lane * 32u];
            unsigned int v;
            do { v = ld_acquire(fp); } while ((int)(v - e) < 0);
        }
        __syncthreads();
    };

    arrive(++ep);                 // init: t zeroing visible fold-wide
    wait_fold(ep);

    for (int i = 1; i < SEQ; ++i) {
        const int buf = i & 1;

        // ---- stage 1: a = relu(W1 [p;x_i] + b1), W1 in registers ----
        {
            const float4* pp = reinterpret_cast<const float4*>(s.p_s);
            const float4* xx = reinterpret_cast<const float4*>(s.x_s[buf]);
            float accA = 0.0f, accB = 0.0f;
            #pragma unroll
            for (int q = 0; q < 8; q += 2) {
                float4 w0 = w1reg[q],   h0 = pp[lg + 16 * q];
                float4 w1 = w1reg[q+1], h1 = pp[lg + 16 * (q+1)];
                accA += w0.x*h0.x + w0.y*h0.y + w0.z*h0.z + w0.w*h0.w;
                accB += w1.x*h1.x + w1.y*h1.y + w1.z*h1.z + w1.w*h1.w;
            }
            #pragma unroll
            for (int q = 8; q < 16; q += 2) {
                float4 w0 = w1reg[q],   h0 = xx[lg + 16 * (q-8)];
                float4 w1 = w1reg[q+1], h1 = xx[lg + 16 * (q-7)];
                accA += w0.x*h0.x + w0.y*h0.y + w0.z*h0.z + w0.w*h0.w;
                accB += w1.x*h1.x + w1.y*h1.y + w1.z*h1.z + w1.w*h1.w;
            }
            float acc = accA + accB;
            acc += __shfl_down_sync(0xffffffffu, acc, 8);
            acc += __shfl_down_sync(0xffffffffu, acc, 4);
            acc += __shfl_down_sync(0xffffffffu, acc, 2);
            acc += __shfl_down_sync(0xffffffffu, acc, 1);
            if (lg == 0) s.a_s[row] = fmaxf(acc + s.b1s[row], 0.0f);
        }
        __syncthreads();

        // prefetch next x + zero next-step t buffer
        if (i + 1 < SEQ) {
            reinterpret_cast<float2*>(s.x_s[(i + 1) & 1])[tid] =
                reinterpret_cast<const float2*>(xsrc + (size_t)(i + 1) * WD)[tid];
        }
        if (tid < HID / NCTA) g_t[fold][(i + 1) & 1][k * (HID / NCTA) + tid] = 0.0f;

        // ---- stage 1b: partial t += W2[:, our cols] @ a_slice (RED to L2) ----
        {
            const int rb = ((tid + (k << 3)) & 255);
            float4 pt = make_float4(0.f, 0.f, 0.f, 0.f);
            #pragma unroll
            for (int c = 0; c < RPC; ++c) {
                float av = s.a_s[c];
                float4 w = reinterpret_cast<const float4*>(&s.W2s[c][0])[rb];
                pt.x += w.x * av; pt.y += w.y * av; pt.z += w.z * av; pt.w += w.w * av;
            }
            float* tg = &g_t[fold][buf][0] + rb * 4;
            atomicAdd(tg + 0, pt.x); atomicAdd(tg + 1, pt.y);
            atomicAdd(tg + 2, pt.z); atomicAdd(tg + 3, pt.w);
        }

        arrive(++ep);             // barrier 1: t partials published
        wait_fold(ep);

        // ---- stage 2: u = tanh(t+b2); p-rows = tanh(W3 u + b3), W3 in registers ----
        {
            float4 t4  = __ldcg(reinterpret_cast<const float4*>(&g_t[fold][buf][0]) + tid);
            float4 b24 = reinterpret_cast<const float4*>(s.b2s)[tid];
            float4 u4;
            u4.x = ftanh(t4.x + b24.x); u4.y = ftanh(t4.y + b24.y);
            u4.z = ftanh(t4.z + b24.z); u4.w = ftanh(t4.w + b24.w);
            reinterpret_cast<float4*>(s.u_s)[tid] = u4;
        }
        __syncthreads();
        {
            const float4* uu = reinterpret_cast<const float4*>(s.u_s);
            float accA = 0.0f, accB = 0.0f;
            #pragma unroll
            for (int q = 0; q < 16; q += 2) {
                float4 w0 = w3reg[q],   h0 = uu[lg + 16 * q];
                float4 w1 = w3reg[q+1], h1 = uu[lg + 16 * (q+1)];
                accA += w0.x*h0.x + w0.y*h0.y + w0.z*h0.z + w0.w*h0.w;
                accB += w1.x*h1.x + w1.y*h1.y + w1.z*h1.z + w1.w*h1.w;
            }
            float acc = accA + accB;
            acc += __shfl_down_sync(0xffffffffu, acc, 8);
            acc += __shfl_down_sync(0xffffffffu, acc, 4);
            acc += __shfl_down_sync(0xffffffffu, acc, 2);
            acc += __shfl_down_sync(0xffffffffu, acc, 1);
            if (lg == 0) g_pv[fold][r0 + row] = ftanh(acc + s.b3s[row]);
        }

        if (i < SEQ - 1) {
            arrive(++ep);         // barrier 2: p published
            wait_fold(ep);
            reinterpret_cast<float2*>(s.p_s)[tid] =
                __ldcg(reinterpret_cast<const float2*>(&g_pv[fold][0]) + tid);
            __syncthreads();
        }
    }

    // ---------------- fused epilogue ----------------
    arrive(++ep);                 // final: p (both folds) published

    if (cta == 0) {
        // wait for ALL 64 CTAs (both folds share the same final epoch count)
        if (warp == 0) {
            const unsigned int* f0 = &g_flags[(unsigned)lane * 32u];
            const unsigned int* f1 = &g_flags[(unsigned)(lane + 32) * 32u];
            unsigned int v;
            do { v = ld_acquire(f0); } while ((int)(v - ep) < 0);
            do { v = ld_acquire(f1); } while ((int)(v - ep) < 0);
        }
        __syncthreads();

        if (warp < 5) {
            float acc = 0.0f;
            const float* w = W4g + warp * (2 * WD);
            for (int j = lane; j < 2 * WD; j += 32) {
                float h = (j < WD) ? __ldcg(&g_pv[0][j]) : __ldcg(&g_pv[1][j - WD]);
                acc += w[j] * h;
            }
            #pragma unroll
            for (int o = 16; o > 0; o >>= 1) acc += __shfl_down_sync(0xffffffffu, acc, o);
            if (lane == 0) s.lgst[warp] = acc + b4g[warp];
        }
        __syncthreads();
        if (tid == 0) {
            float m = s.lgst[0];
            #pragma unroll
            for (int c = 1; c < 5; ++c) m = fmaxf(m, s.lgst[c]);
            float ssum = 0.0f;
            #pragma unroll
            for (int c = 0; c < 5; ++c) ssum += expf(s.lgst[c] - m);
            float lse = m + logf(ssum);
            #pragma unroll
            for (int c = 0; c < 5; ++c) out[c] = s.lgst[c] - lse;
        }
    }
}

extern "C" void kernel_launch(void* const* d_in, const int* in_sizes, int n_in,
                              void* d_out, int out_size)
{
    const float* input  = (const float*)d_in[0];
    const float* input2 = (const float*)d_in[1];
    const int off = (n_in >= 11) ? 3 : 2;
    const float* W1 = (const float*)d_in[off + 0];
    const float* b1 = (const float*)d_in[off + 1];
    const float* W2 = (const float*)d_in[off + 2];
    const float* b2 = (const float*)d_in[off + 3];
    const float* W3 = (const float*)d_in[off + 4];
    const float* b3 = (const float*)d_in[off + 5];
    const float* W4 = (const float*)d_in[off + 6];
    const float* b4 = (const float*)d_in[off + 7];

    cudaFuncSetAttribute(rnn_fold_kernel,
                         cudaFuncAttributeMaxDynamicSharedMemorySize,
                         (int)sizeof(Smem));

    rnn_fold_kernel<<<NFOLD * NCTA, THREADS, sizeof(Smem)>>>(
        input, input2, W1, b1, W2, b2, W3, b3, W4, b4, (float*)d_out);
}

// round 5
// speedup vs baseline: 1.4801x; 1.0593x over previous
#include <cuda_runtime.h>
#include <cuda_bf16.h>

#define SEQ    32768
#define WD     512
#define HID    1024
#define NCTA   64          // CTAs per fold
#define NFOLD  2
#define ARPC   8           // a/p rows per CTA  (512/64)
#define TRPC   16          // t rows per CTA    (1024/64)
#define THREADS 256

// Exchange buffers: one 128B line per producer CTA (slice + padding)
__device__ float        g_a[NFOLD][NCTA][32];
__device__ float        g_u[NFOLD][NCTA][32];
__device__ float        g_p[NFOLD][NCTA][32];
__device__ unsigned int g_flags[NFOLD * NCTA * 32];   // 128B-strided epoch flags

__device__ __forceinline__ void st_release(unsigned int* p, unsigned int v) {
    asm volatile("st.release.gpu.global.u32 [%0], %1;" :: "l"(p), "r"(v) : "memory");
}
__device__ __forceinline__ unsigned int ld_acquire(const unsigned int* p) {
    unsigned int v;
    asm volatile("ld.acquire.gpu.global.u32 %0, [%1];" : "=r"(v) : "l"(p) : "memory");
    return v;
}

// tanh with ~1e-7 abs error: 1 - 2/(e^{2x}+1)
__device__ __forceinline__ float ftanh(float x) {
    float e = __expf(2.0f * x);
    return 1.0f - __fdividef(2.0f, e + 1.0f);
}

__device__ __forceinline__ float dot4(float4 w, float4 h) {
    return w.x*h.x + w.y*h.y + w.z*h.z + w.w*h.w;
}

struct Smem {
    float p_s[WD];
    float x_s[2][WD];
    float a_s[WD];
    float u_s[HID];
    float b2s[TRPC];
    float b1s[ARPC];
    float b3s[ARPC];
    float lgst[8];
};

__global__ void __launch_bounds__(THREADS, 1)
rnn_fold_kernel(const float* __restrict__ input,
                const float* __restrict__ input2,
                const float* __restrict__ W1g, const float* __restrict__ b1g,
                const float* __restrict__ W2g, const float* __restrict__ b2g,
                const float* __restrict__ W3g, const float* __restrict__ b3g,
                const float* __restrict__ W4g, const float* __restrict__ b4g,
                float* __restrict__ out)
{
    __shared__ Smem s;

    const int tid  = threadIdx.x;
    const int lane = tid & 31;
    const int warp = tid >> 5;        // 0..7
    const int cta  = blockIdx.x;
    const int fold = cta / NCTA;
    const int k    = cta % NCTA;
    const float* xsrc = (fold == 0) ? input : input2;

    const int arow0 = k * ARPC;       // global a/p row base
    const int trow0 = k * TRPC;       // global t row base

    // stage2 thread mapping: 2 t-rows per warp, 16 lanes per row
    const int row16 = (warp << 1) | (lane >> 4);   // 0..15 local t-row
    const int lg16  = lane & 15;

    // ---------------- weights -> registers ----------------
    float4 w1reg[8], w2reg[8], w3reg[8];
    {
        const float4* w1row = reinterpret_cast<const float4*>(W1g + (size_t)(arow0 + warp) * HID);
        const float4* w3row = reinterpret_cast<const float4*>(W3g + (size_t)(arow0 + warp) * HID);
        #pragma unroll
        for (int q = 0; q < 8; ++q) {
            w1reg[q] = w1row[lane + 32 * q];
            w3reg[q] = w3row[lane + 32 * q];
        }
        const float4* w2row = reinterpret_cast<const float4*>(W2g + (size_t)(trow0 + row16) * WD);
        #pragma unroll
        for (int q = 0; q < 8; ++q) w2reg[q] = w2row[lg16 + 16 * q];
    }

    // ---------------- biases + initial vectors ----------------
    if (tid < ARPC)  { s.b1s[tid] = b1g[arow0 + tid]; s.b3s[tid] = b3g[arow0 + tid]; }
    if (tid < TRPC)  { s.b2s[tid] = b2g[trow0 + tid]; }
    {
        // p0 = x[0]; x buffer 1 = x[1]
        reinterpret_cast<float2*>(s.p_s)[tid]    = reinterpret_cast<const float2*>(xsrc)[tid];
        reinterpret_cast<float2*>(s.x_s[1])[tid] = reinterpret_cast<const float2*>(xsrc + WD)[tid];
    }

    unsigned int* my_flag = &g_flags[(unsigned)cta * 32u];
    const unsigned int fold_flag0 = (unsigned)(fold * NCTA) * 32u;
    const unsigned int base = ld_acquire(my_flag);   // replay-safe monotonic epoch
    unsigned int ep = base;
    __syncthreads();

    auto arrive = [&]() {
        __syncthreads();
        ++ep;
        if (tid == 0) st_release(my_flag, ep);
    };
    auto wait_fold = [&]() {
        if (warp == 0) {
            const unsigned int* f0 = &g_flags[fold_flag0 + (unsigned)lane * 32u];
            const unsigned int* f1 = f0 + 32u * 32u;
            unsigned int v0, v1;
            do { v0 = ld_acquire(f0); } while ((int)(v0 - ep) < 0);
            do { v1 = ld_acquire(f1); } while ((int)(v1 - ep) < 0);
        }
        __syncthreads();
    };

    for (int i = 1; i < SEQ; ++i) {
        const int buf = i & 1;

        // ---- stage 1: a-rows = relu(W1[arow] . [p;x]) ; warp-per-row ----
        {
            const float4* pp = reinterpret_cast<const float4*>(s.p_s);
            const float4* xx = reinterpret_cast<const float4*>(s.x_s[buf]);
            float accA = 0.f, accB = 0.f;
            #pragma unroll
            for (int q = 0; q < 4; ++q) accA += dot4(w1reg[q], pp[lane + 32 * q]);
            #pragma unroll
            for (int q = 4; q < 8; ++q) accB += dot4(w1reg[q], xx[lane + 32 * q - 128]);
            float acc = accA + accB;
            #pragma unroll
            for (int o = 16; o > 0; o >>= 1) acc += __shfl_xor_sync(0xffffffffu, acc, o);
            if (lane == 0)
                __stcg(&g_a[fold][k][warp], fmaxf(acc + s.b1s[warp], 0.0f));
        }
        arrive();                                 // B1: a slices published

        // prefetch next x while polling
        if (i + 1 < SEQ) {
            reinterpret_cast<float2*>(s.x_s[buf ^ 1])[tid] =
                reinterpret_cast<const float2*>(xsrc + (size_t)(i + 1) * WD)[tid];
        }
        wait_fold();

        // gather full a (512) into smem: 2 consecutive elements per thread
        {
            float2 av = __ldcg(reinterpret_cast<const float2*>(&g_a[fold][tid >> 2][(tid & 3) * 2]));
            reinterpret_cast<float2*>(s.a_s)[tid] = av;
        }
        __syncthreads();

        // ---- stage 2: u-rows = tanh(W2[trow] . a + b2) ; 2 rows/warp ----
        {
            const float4* aa = reinterpret_cast<const float4*>(s.a_s);
            float acc = 0.f;
            #pragma unroll
            for (int q = 0; q < 8; ++q) acc += dot4(w2reg[q], aa[lg16 + 16 * q]);
            #pragma unroll
            for (int o = 8; o > 0; o >>= 1) acc += __shfl_xor_sync(0xffffffffu, acc, o);
            if (lg16 == 0)
                __stcg(&g_u[fold][k][row16], ftanh(acc + s.b2s[row16]));
        }
        arrive();                                 // B2: u slices published
        wait_fold();

        // gather full u (1024): 4 consecutive elements per thread
        {
            float4 uv = __ldcg(reinterpret_cast<const float4*>(&g_u[fold][tid >> 2][(tid & 3) * 4]));
            reinterpret_cast<float4*>(s.u_s)[tid] = uv;
        }
        __syncthreads();

        // ---- stage 3: p-rows = tanh(W3[arow] . u + b3) ; warp-per-row ----
        {
            const float4* uu = reinterpret_cast<const float4*>(s.u_s);
            float accA = 0.f, accB = 0.f;
            #pragma unroll
            for (int q = 0; q < 4; ++q) accA += dot4(w3reg[q], uu[lane + 32 * q]);
            #pragma unroll
            for (int q = 4; q < 8; ++q) accB += dot4(w3reg[q], uu[lane + 32 * q]);
            float acc = accA + accB;
            #pragma unroll
            for (int o = 16; o > 0; o >>= 1) acc += __shfl_xor_sync(0xffffffffu, acc, o);
            if (lane == 0)
                __stcg(&g_p[fold][k][warp], ftanh(acc + s.b3s[warp]));
        }
        arrive();                                 // B3: p slices published

        if (i < SEQ - 1) {
            wait_fold();
            float2 pv = __ldcg(reinterpret_cast<const float2*>(&g_p[fold][tid >> 2][(tid & 3) * 2]));
            reinterpret_cast<float2*>(s.p_s)[tid] = pv;
            __syncthreads();
        }
    }

    // ---------------- fused epilogue (CTA 0 waits on ALL 128 CTAs) ----------------
    if (cta == 0) {
        if (warp == 0) {
            #pragma unroll
            for (int m = 0; m < 4; ++m) {
                const unsigned int* fp = &g_flags[(unsigned)(lane + 32 * m) * 32u];
                unsigned int v;
                do { v = ld_acquire(fp); } while ((int)(v - ep) < 0);
            }
        }
        __syncthreads();

        if (warp < 5) {
            float acc = 0.0f;
            const float* w = W4g + warp * (2 * WD);
            for (int j = lane; j < 2 * WD; j += 32) {
                int f  = (j < WD) ? 0 : 1;
                int jj = (j < WD) ? j : j - WD;
                float h = __ldcg(&g_p[f][jj >> 3][jj & 7]);
                acc += w[j] * h;
            }
            #pragma unroll
            for (int o = 16; o > 0; o >>= 1) acc += __shfl_down_sync(0xffffffffu, acc, o);
            if (lane == 0) s.lgst[warp] = acc + b4g[warp];
        }
        __syncthreads();
        if (tid == 0) {
            float m = s.lgst[0];
            #pragma unroll
            for (int c = 1; c < 5; ++c) m = fmaxf(m, s.lgst[c]);
            float ssum = 0.0f;
            #pragma unroll
            for (int c = 0; c < 5; ++c) ssum += expf(s.lgst[c] - m);
            float lse = m + logf(ssum);
            #pragma unroll
            for (int c = 0; c < 5; ++c) out[c] = s.lgst[c] - lse;
        }
    }
}

extern "C" void kernel_launch(void* const* d_in, const int* in_sizes, int n_in,
                              void* d_out, int out_size)
{
    const float* input  = (const float*)d_in[0];
    const float* input2 = (const float*)d_in[1];
    const int off = (n_in >= 11) ? 3 : 2;
    const float* W1 = (const float*)d_in[off + 0];
    const float* b1 = (const float*)d_in[off + 1];
    const float* W2 = (const float*)d_in[off + 2];
    const float* b2 = (const float*)d_in[off + 3];
    const float* W3 = (const float*)d_in[off + 4];
    const float* b3 = (const float*)d_in[off + 5];
    const float* W4 = (const float*)d_in[off + 6];
    const float* b4 = (const float*)d_in[off + 7];

    rnn_fold_kernel<<<NFOLD * NCTA, THREADS>>>(
        input, input2, W1, b1, W2, b2, W3, b3, W4, b4, (float*)d_out);
}

// round 6
// speedup vs baseline: 2.0600x; 1.3918x over previous
#include <cuda_runtime.h>
#include <cuda_bf16.h>

#define SEQ    32768
#define WD     512
#define HID    1024
#define NCTA   64          // CTAs per fold
#define NFOLD  2
#define ARPC   8           // a/p rows per CTA
#define TRPC   16          // t rows per CTA
#define THREADS 256

typedef unsigned long long ull;

// Tag-embedded exchange slots: (tag<<32)|value_bits, one 32B sector per slot.
__device__ ull g_aslot[NFOLD][WD][4];
__device__ ull g_uslot[NFOLD][HID][4];
__device__ ull g_pslot[NFOLD][WD][4];
__device__ unsigned int g_epoch_base;   // bumped once per launch by CTA 0

__device__ __forceinline__ ull ldr64(const ull* p) {
    ull v; asm volatile("ld.relaxed.gpu.global.b64 %0, [%1];" : "=l"(v) : "l"(p) : "memory");
    return v;
}
__device__ __forceinline__ void str64(ull* p, ull v) {
    asm volatile("st.relaxed.gpu.global.b64 [%0], %1;" :: "l"(p), "l"(v) : "memory");
}
__device__ __forceinline__ ull pack(unsigned tag, float v) {
    return ((ull)tag << 32) | (ull)__float_as_uint(v);
}

// Poll N slots concurrently (MLP=N per sweep) until each tag >= want.
template <int N>
__device__ __forceinline__ void poll_slots(const ull* const (&sl)[N], unsigned want, float (&out)[N]) {
    unsigned pending = (1u << N) - 1u;
    ull v[N];
    while (pending) {
        #pragma unroll
        for (int j = 0; j < N; ++j)
            if (pending & (1u << j)) v[j] = ldr64(sl[j]);
        #pragma unroll
        for (int j = 0; j < N; ++j)
            if (pending & (1u << j))
                if ((int)((unsigned)(v[j] >> 32) - want) >= 0) pending &= ~(1u << j);
    }
    #pragma unroll
    for (int j = 0; j < N; ++j) out[j] = __uint_as_float((unsigned)(v[j] & 0xffffffffu));
}

// tanh with ~1e-7 abs error: 1 - 2/(e^{2x}+1)
__device__ __forceinline__ float ftanh(float x) {
    float e = __expf(2.0f * x);
    return 1.0f - __fdividef(2.0f, e + 1.0f);
}
__device__ __forceinline__ float dot4(float4 w, float4 h) {
    return w.x*h.x + w.y*h.y + w.z*h.z + w.w*h.w;
}

struct Smem {
    float p_s[WD];
    float x_s[2][WD];
    float a_s[WD];
    float u_s[HID];       // also reused for [p0;p1] in the epilogue
    float lgst[8];
};

__global__ void __launch_bounds__(THREADS, 1)
rnn_fold_kernel(const float* __restrict__ input,
                const float* __restrict__ input2,
                const float* __restrict__ W1g, const float* __restrict__ b1g,
                const float* __restrict__ W2g, const float* __restrict__ b2g,
                const float* __restrict__ W3g, const float* __restrict__ b3g,
                const float* __restrict__ W4g, const float* __restrict__ b4g,
                float* __restrict__ out)
{
    __shared__ Smem s;

    const int tid  = threadIdx.x;
    const int lane = tid & 31;
    const int warp = tid >> 5;        // 0..7
    const int cta  = blockIdx.x;
    const int fold = cta / NCTA;
    const int k    = cta % NCTA;
    const float* xsrc = (fold == 0) ? input : input2;

    const int arow0 = k * ARPC;       // global a/p row base
    const int trow0 = k * TRPC;       // global t row base

    const int row16 = (warp << 1) | (lane >> 4);   // local t-row (0..15)
    const int lg16  = lane & 15;

    // ---------------- weights -> registers ----------------
    float4 w1reg[8], w2reg[8], w3reg[8];
    {
        const float4* w1row = reinterpret_cast<const float4*>(W1g + (size_t)(arow0 + warp) * HID);
        const float4* w3row = reinterpret_cast<const float4*>(W3g + (size_t)(arow0 + warp) * HID);
        #pragma unroll
        for (int q = 0; q < 8; ++q) {
            w1reg[q] = w1row[lane + 32 * q];
            w3reg[q] = w3row[lane + 32 * q];
        }
        const float4* w2row = reinterpret_cast<const float4*>(W2g + (size_t)(trow0 + row16) * WD);
        #pragma unroll
        for (int q = 0; q < 8; ++q) w2reg[q] = w2row[lg16 + 16 * q];
    }
    const float b1r = b1g[arow0 + warp];
    const float b3r = b3g[arow0 + warp];
    const float b2r = b2g[trow0 + row16];

    // initial vectors: p0 = x[0], x buffer 1 = x[1]
    reinterpret_cast<float2*>(s.p_s)[tid]    = reinterpret_cast<const float2*>(xsrc)[tid];
    reinterpret_cast<float2*>(s.x_s[1])[tid] = reinterpret_cast<const float2*>(xsrc + WD)[tid];

    unsigned int base;
    asm volatile("ld.relaxed.gpu.global.u32 %0, [%1];" : "=r"(base) : "l"(&g_epoch_base) : "memory");
    __syncthreads();

    for (int i = 1; i < SEQ; ++i) {
        const int buf = i & 1;
        const unsigned t1 = base + 3u * (unsigned)(i - 1) + 1u;

        // prefetch next x into registers (latency hidden across the step)
        float2 xn = make_float2(0.f, 0.f);
        const bool hasx = (i + 1 < SEQ);
        if (hasx) xn = __ldcg(reinterpret_cast<const float2*>(xsrc + (size_t)(i + 1) * WD) + tid);

        // ---- stage 1: a-row = relu(W1[arow0+warp] . [p;x]) ----
        {
            const float4* pp = reinterpret_cast<const float4*>(s.p_s);
            const float4* xx = reinterpret_cast<const float4*>(s.x_s[buf]);
            float accA = 0.f, accB = 0.f;
            #pragma unroll
            for (int q = 0; q < 4; ++q) accA += dot4(w1reg[q], pp[lane + 32 * q]);
            #pragma unroll
            for (int q = 4; q < 8; ++q) accB += dot4(w1reg[q], xx[lane + 32 * q - 128]);
            float acc = accA + accB;
            #pragma unroll
            for (int o = 16; o > 0; o >>= 1) acc += __shfl_xor_sync(0xffffffffu, acc, o);
            if (lane == 0)
                str64(&g_aslot[fold][arow0 + warp][0], pack(t1, fmaxf(acc + b1r, 0.0f)));
        }

        // ---- gather a (dataflow poll: 2 slots/thread) ----
        {
            const ull* sl[2] = { &g_aslot[fold][tid][0], &g_aslot[fold][tid + 256][0] };
            float av[2];
            poll_slots(sl, t1, av);
            s.a_s[tid]       = av[0];
            s.a_s[tid + 256] = av[1];
        }
        if (hasx) reinterpret_cast<float2*>(s.x_s[buf ^ 1])[tid] = xn;
        __syncthreads();

        // ---- stage 2: u-row = tanh(W2[trow0+row16] . a + b2) ----
        {
            const float4* aa = reinterpret_cast<const float4*>(s.a_s);
            float acc = 0.f;
            #pragma unroll
            for (int q = 0; q < 8; ++q) acc += dot4(w2reg[q], aa[lg16 + 16 * q]);
            #pragma unroll
            for (int o = 8; o > 0; o >>= 1) acc += __shfl_xor_sync(0xffffffffu, acc, o);
            if (lg16 == 0)
                str64(&g_uslot[fold][trow0 + row16][0], pack(t1 + 1u, ftanh(acc + b2r)));
        }

        // ---- gather u (4 slots/thread) ----
        {
            const ull* sl[4] = { &g_uslot[fold][tid][0],       &g_uslot[fold][tid + 256][0],
                                 &g_uslot[fold][tid + 512][0], &g_uslot[fold][tid + 768][0] };
            float uv[4];
            poll_slots(sl, t1 + 1u, uv);
            s.u_s[tid]       = uv[0];
            s.u_s[tid + 256] = uv[1];
            s.u_s[tid + 512] = uv[2];
            s.u_s[tid + 768] = uv[3];
        }
        __syncthreads();

        // ---- stage 3: p-row = tanh(W3[arow0+warp] . u + b3) ----
        {
            const float4* uu = reinterpret_cast<const float4*>(s.u_s);
            float accA = 0.f, accB = 0.f;
            #pragma unroll
            for (int q = 0; q < 4; ++q) accA += dot4(w3reg[q], uu[lane + 32 * q]);
            #pragma unroll
            for (int q = 4; q < 8; ++q) accB += dot4(w3reg[q], uu[lane + 32 * q]);
            float acc = accA + accB;
            #pragma unroll
            for (int o = 16; o > 0; o >>= 1) acc += __shfl_xor_sync(0xffffffffu, acc, o);
            if (lane == 0)
                str64(&g_pslot[fold][arow0 + warp][0], pack(t1 + 2u, ftanh(acc + b3r)));
        }

        // ---- gather p (2 slots/thread) ----
        if (i < SEQ - 1) {
            const ull* sl[2] = { &g_pslot[fold][tid][0], &g_pslot[fold][tid + 256][0] };
            float pv[2];
            poll_slots(sl, t1 + 2u, pv);
            s.p_s[tid]       = pv[0];
            s.p_s[tid + 256] = pv[1];
            __syncthreads();
        }
    }

    // ---------------- fused epilogue: CTA 0 gathers both folds' final p ----------------
    if (cta == 0) {
        const unsigned tfin = base + 3u * (unsigned)(SEQ - 2) + 3u;
        {
            const ull* sl[4] = { &g_pslot[0][tid][0], &g_pslot[0][tid + 256][0],
                                 &g_pslot[1][tid][0], &g_pslot[1][tid + 256][0] };
            float pv[4];
            poll_slots(sl, tfin, pv);
            s.u_s[tid]             = pv[0];
            s.u_s[tid + 256]       = pv[1];
            s.u_s[512 + tid]       = pv[2];
            s.u_s[512 + tid + 256] = pv[3];
        }
        __syncthreads();

        if (warp < 5) {
            float acc = 0.0f;
            const float* w = W4g + warp * (2 * WD);
            for (int j = lane; j < 2 * WD; j += 32) acc += w[j] * s.u_s[j];
            #pragma unroll
            for (int o = 16; o > 0; o >>= 1) acc += __shfl_down_sync(0xffffffffu, acc, o);
            if (lane == 0) s.lgst[warp] = acc + b4g[warp];
        }
        __syncthreads();
        if (tid == 0) {
            float m = s.lgst[0];
            #pragma unroll
            for (int c = 1; c < 5; ++c) m = fmaxf(m, s.lgst[c]);
            float ssum = 0.0f;
            #pragma unroll
            for (int c = 0; c < 5; ++c) ssum += expf(s.lgst[c] - m);
            float lse = m + logf(ssum);
            #pragma unroll
            for (int c = 0; c < 5; ++c) out[c] = s.lgst[c] - lse;
            // bump epoch base for the next (graph-replayed) launch
            unsigned nb = base + 3u * (unsigned)SEQ;
            asm volatile("st.relaxed.gpu.global.u32 [%0], %1;" :: "l"(&g_epoch_base), "r"(nb) : "memory");
        }
    }
}

extern "C" void kernel_launch(void* const* d_in, const int* in_sizes, int n_in,
                              void* d_out, int out_size)
{
    const float* input  = (const float*)d_in[0];
    const float* input2 = (const float*)d_in[1];
    const int off = (n_in >= 11) ? 3 : 2;
    const float* W1 = (const float*)d_in[off + 0];
    const float* b1 = (const float*)d_in[off + 1];
    const float* W2 = (const float*)d_in[off + 2];
    const float* b2 = (const float*)d_in[off + 3];
    const float* W3 = (const float*)d_in[off + 4];
    const float* b3 = (const float*)d_in[off + 5];
    const float* W4 = (const float*)d_in[off + 6];
    const float* b4 = (const float*)d_in[off + 7];

    rnn_fold_kernel<<<NFOLD * NCTA, THREADS>>>(
        input, input2, W1, b1, W2, b2, W3, b3, W4, b4, (float*)d_out);
}

// round 8
// speedup vs baseline: 2.7492x; 1.3346x over previous
#include <cuda_runtime.h>
#include <cuda_bf16.h>

#define SEQ    32768
#define WD     512
#define HID    1024
#define NCTA   64          // CTAs per fold
#define NFOLD  2
#define ARPC   8           // a/p rows per CTA
#define TRPC   16          // t rows per CTA
#define THREADS 256

typedef unsigned long long ull;

// Packed tag-embedded exchange slots: (tag<<32)|value_bits, 8B stride.
__device__ ull g_aslot[NFOLD][WD];
__device__ ull g_uslot[NFOLD][HID];
__device__ ull g_pslot[NFOLD][WD];
__device__ unsigned int g_epoch_base;   // bumped once per launch by CTA 0

__device__ __forceinline__ ull ldr64(const ull* p) {
    ull v; asm volatile("ld.relaxed.gpu.global.b64 %0, [%1];" : "=l"(v) : "l"(p) : "memory");
    return v;
}
__device__ __forceinline__ void str64(ull* p, ull v) {
    asm volatile("st.relaxed.gpu.global.b64 [%0], %1;" :: "l"(p), "l"(v) : "memory");
}
__device__ __forceinline__ ull pack(unsigned tag, float v) {
    return ((ull)tag << 32) | (ull)__float_as_uint(v);
}

// Poll N slots concurrently (MLP=N per sweep) until each tag >= want.
template <int N>
__device__ __forceinline__ void poll_slots(const ull* const (&sl)[N], unsigned want, float (&out)[N]) {
    unsigned pending = (1u << N) - 1u;
    ull v[N];
    while (pending) {
        #pragma unroll
        for (int j = 0; j < N; ++j)
            if (pending & (1u << j)) v[j] = ldr64(sl[j]);
        #pragma unroll
        for (int j = 0; j < N; ++j)
            if (pending & (1u << j))
                if ((int)((unsigned)(v[j] >> 32) - want) >= 0) pending &= ~(1u << j);
    }
    #pragma unroll
    for (int j = 0; j < N; ++j) out[j] = __uint_as_float((unsigned)(v[j] & 0xffffffffu));
}

// tanh with ~1e-7 abs error: 1 - 2/(e^{2x}+1)
__device__ __forceinline__ float ftanh(float x) {
    float e = __expf(2.0f * x);
    return 1.0f - __fdividef(2.0f, e + 1.0f);
}
__device__ __forceinline__ float dot4(float4 w, float4 h) {
    return w.x*h.x + w.y*h.y + w.z*h.z + w.w*h.w;
}

struct Smem {
    float p_s[WD];
    float x_s[2][WD];     // double-buffered x
    float a_s[WD];
    float u_s[HID];       // reused for [p0;p1] in the epilogue
    float lgst[8];
};

__global__ void __launch_bounds__(THREADS, 1)
rnn_fold_kernel(const float* __restrict__ input,
                const float* __restrict__ input2,
                const float* __restrict__ W1g, const float* __restrict__ b1g,
                const float* __restrict__ W2g, const float* __restrict__ b2g,
                const float* __restrict__ W3g, const float* __restrict__ b3g,
                const float* __restrict__ W4g, const float* __restrict__ b4g,
                float* __restrict__ out)
{
    __shared__ Smem s;

    const int tid  = threadIdx.x;
    const int lane = tid & 31;
    const int warp = tid >> 5;        // 0..7
    const int cta  = blockIdx.x;
    const int fold = cta / NCTA;
    const int k    = cta % NCTA;
    const float* xsrc = (fold == 0) ? input : input2;

    const int arow0 = k * ARPC;       // global a/p row base
    const int trow0 = k * TRPC;       // global t row base

    const int row16 = (warp << 1) | (lane >> 4);   // local t-row (0..15)
    const int lg16  = lane & 15;

    // ---------------- weights -> registers ----------------
    float4 w1reg[8], w2reg[8], w3reg[8];
    {
        const float4* w1row = reinterpret_cast<const float4*>(W1g + (size_t)(arow0 + warp) * HID);
        const float4* w3row = reinterpret_cast<const float4*>(W3g + (size_t)(arow0 + warp) * HID);
        #pragma unroll
        for (int q = 0; q < 8; ++q) {
            w1reg[q] = w1row[lane + 32 * q];
            w3reg[q] = w3row[lane + 32 * q];
        }
        const float4* w2row = reinterpret_cast<const float4*>(W2g + (size_t)(trow0 + row16) * WD);
        #pragma unroll
        for (int q = 0; q < 8; ++q) w2reg[q] = w2row[lg16 + 16 * q];
    }
    const float b1r = b1g[arow0 + warp];
    const float b3r = b3g[arow0 + warp];
    const float b2r = b2g[trow0 + row16];

    // initial vectors: p0 = x[0], x buffer 1 = x[1]
    reinterpret_cast<float2*>(s.p_s)[tid]    = reinterpret_cast<const float2*>(xsrc)[tid];
    reinterpret_cast<float2*>(s.x_s[1])[tid] = reinterpret_cast<const float2*>(xsrc + WD)[tid];

    unsigned int base;
    asm volatile("ld.relaxed.gpu.global.u32 %0, [%1];" : "=r"(base) : "l"(&g_epoch_base) : "memory");
    __syncthreads();

    // xacc for step 1: per-lane partial of (W1 x-half) . x[1]
    float xacc = 0.0f;
    {
        const float4* xx = reinterpret_cast<const float4*>(s.x_s[1]);
        #pragma unroll
        for (int q = 0; q < 4; ++q) xacc += dot4(w1reg[4 + q], xx[lane + 32 * q]);
    }

    for (int i = 1; i < SEQ; ++i) {
        const int buf = i & 1;
        const unsigned t1 = base + 3u * (unsigned)(i - 1) + 1u;
        const bool hasx = (i + 1 < SEQ);

        // prefetch next x into registers
        float2 xn = make_float2(0.f, 0.f);
        if (hasx) xn = __ldcg(reinterpret_cast<const float2*>(xsrc + (size_t)(i + 1) * WD) + tid);

        // ---- stage 1 (critical path = p-half only): a-row = relu(W1p.p + xacc + b1) ----
        {
            const float4* pp = reinterpret_cast<const float4*>(s.p_s);
            float acc = xacc;
            #pragma unroll
            for (int q = 0; q < 4; ++q) acc += dot4(w1reg[q], pp[lane + 32 * q]);
            #pragma unroll
            for (int o = 16; o > 0; o >>= 1) acc += __shfl_xor_sync(0xffffffffu, acc, o);
            if (lane == 0)
                str64(&g_aslot[fold][arow0 + warp], pack(t1, fmaxf(acc + b1r, 0.0f)));
        }

        // stash next x into the other buffer (read only after the a-gather sync)
        if (hasx) reinterpret_cast<float2*>(s.x_s[buf ^ 1])[tid] = xn;

        // ---- gather a: 2 packed slots / thread ----
        {
            const ull* sl[2] = { &g_aslot[fold][2 * tid], &g_aslot[fold][2 * tid + 1] };
            float av[2];
            poll_slots(sl, t1, av);
            reinterpret_cast<float2*>(s.a_s)[tid] = make_float2(av[0], av[1]);
        }
        __syncthreads();

        // ---- stage 2: u-row = tanh(W2.a + b2) ----
        {
            const float4* aa = reinterpret_cast<const float4*>(s.a_s);
            float acc = 0.f;
            #pragma unroll
            for (int q = 0; q < 8; ++q) acc += dot4(w2reg[q], aa[lg16 + 16 * q]);
            #pragma unroll
            for (int o = 8; o > 0; o >>= 1) acc += __shfl_xor_sync(0xffffffffu, acc, o);
            if (lg16 == 0)
                str64(&g_uslot[fold][trow0 + row16], pack(t1 + 1u, ftanh(acc + b2r)));
        }

        // xacc for NEXT step (shadow of the u-exchange), from the freshly stashed buffer
        if (hasx) {
            const float4* xx = reinterpret_cast<const float4*>(s.x_s[buf ^ 1]);
            float xa = 0.f;
            #pragma unroll
            for (int q = 0; q < 4; ++q) xa += dot4(w1reg[4 + q], xx[lane + 32 * q]);
            xacc = xa;
        }

        // ---- gather u: 4 packed slots / thread ----
        {
            const ull* sl[4] = { &g_uslot[fold][2 * tid],       &g_uslot[fold][2 * tid + 1],
                                 &g_uslot[fold][512 + 2 * tid], &g_uslot[fold][512 + 2 * tid + 1] };
            float uv[4];
            poll_slots(sl, t1 + 1u, uv);
            reinterpret_cast<float2*>(s.u_s)[tid]       = make_float2(uv[0], uv[1]);
            reinterpret_cast<float2*>(s.u_s + 512)[tid] = make_float2(uv[2], uv[3]);
        }
        __syncthreads();

        // ---- stage 3: p-row = tanh(W3.u + b3) ----
        {
            const float4* uu = reinterpret_cast<const float4*>(s.u_s);
            float accA = 0.f, accB = 0.f;
            #pragma unroll
            for (int q = 0; q < 4; ++q) accA += dot4(w3reg[q], uu[lane + 32 * q]);
            #pragma unroll
            for (int q = 4; q < 8; ++q) accB += dot4(w3reg[q], uu[lane + 32 * q]);
            float acc = accA + accB;
            #pragma unroll
            for (int o = 16; o > 0; o >>= 1) acc += __shfl_xor_sync(0xffffffffu, acc, o);
            if (lane == 0)
                str64(&g_pslot[fold][arow0 + warp], pack(t1 + 2u, ftanh(acc + b3r)));
        }

        // ---- gather p: 2 packed slots / thread ----
        if (i < SEQ - 1) {
            const ull* sl[2] = { &g_pslot[fold][2 * tid], &g_pslot[fold][2 * tid + 1] };
            float pv[2];
            poll_slots(sl, t1 + 2u, pv);
            reinterpret_cast<float2*>(s.p_s)[tid] = make_float2(pv[0], pv[1]);
            __syncthreads();
        }
    }

    // ---------------- fused epilogue: CTA 0 gathers both folds' final p ----------------
    if (cta == 0) {
        const unsigned tfin = base + 3u * (unsigned)(SEQ - 2) + 3u;
        {
            const ull* sl[4] = { &g_pslot[0][2 * tid], &g_pslot[0][2 * tid + 1],
                                 &g_pslot[1][2 * tid], &g_pslot[1][2 * tid + 1] };
            float pv[4];
            poll_slots(sl, tfin, pv);
            reinterpret_cast<float2*>(s.u_s)[tid]       = make_float2(pv[0], pv[1]);
            reinterpret_cast<float2*>(s.u_s + 512)[tid] = make_float2(pv[2], pv[3]);
        }
        __syncthreads();

        if (warp < 5) {
            float acc = 0.0f;
            const float* w = W4g + warp * (2 * WD);
            for (int j = lane; j < 2 * WD; j += 32) acc += w[j] * s.u_s[j];
            #pragma unroll
            for (int o = 16; o > 0; o >>= 1) acc += __shfl_down_sync(0xffffffffu, acc, o);
            if (lane == 0) s.lgst[warp] = acc + b4g[warp];
        }
        __syncthreads();
        if (tid == 0) {
            float m = s.lgst[0];
            #pragma unroll
            for (int c = 1; c < 5; ++c) m = fmaxf(m, s.lgst[c]);
            float ssum = 0.0f;
            #pragma unroll
            for (int c = 0; c < 5; ++c) ssum += expf(s.lgst[c] - m);
            float lse = m + logf(ssum);
            #pragma unroll
            for (int c = 0; c < 5; ++c) out[c] = s.lgst[c] - lse;
            // bump epoch base for the next graph replay (3*SEQ > any tag used)
            unsigned nb = base + 3u * (unsigned)SEQ;
            asm volatile("st.relaxed.gpu.global.u32 [%0], %1;" :: "l"(&g_epoch_base), "r"(nb) : "memory");
        }
    }
}

extern "C" void kernel_launch(void* const* d_in, const int* in_sizes, int n_in,
                              void* d_out, int out_size)
{
    const float* input  = (const float*)d_in[0];
    const float* input2 = (const float*)d_in[1];
    const int off = (n_in >= 11) ? 3 : 2;
    const float* W1 = (const float*)d_in[off + 0];
    const float* b1 = (const float*)d_in[off + 1];
    const float* W2 = (const float*)d_in[off + 2];
    const float* b2 = (const float*)d_in[off + 3];
    const float* W3 = (const float*)d_in[off + 4];
    const float* b3 = (const float*)d_in[off + 5];
    const float* W4 = (const float*)d_in[off + 6];
    const float* b4 = (const float*)d_in[off + 7];

    rnn_fold_kernel<<<NFOLD * NCTA, THREADS>>>(
        input, input2, W1, b1, W2, b2, W3, b3, W4, b4, (float*)d_out);
}